// round 15
// baseline (speedup 1.0000x reference)
#include <cuda_runtime.h>
#include <cstdint>

#define T_LEN 2048
#define B_SZ  256
#define IN_DIM 182
#define G3     192
#define KC     32
#define NCHUNK 6
#define M_TILE 128

typedef unsigned long long ull;

// scratch: IG[B*T,192] (~403MB) + pair-interleaved split-B images [chunk][192][32]
__device__ float g_ig[(size_t)B_SZ * T_LEN * G3];
__device__ __align__(16) float g_bh[NCHUNK * G3 * KC];
__device__ __align__(16) float g_bl[NCHUNK * G3 * KC];

// ---------------- helpers ----------------
__device__ __forceinline__ uint32_t smem_u32(const void* p) {
    uint32_t a;
    asm("{ .reg .u64 t; cvta.to.shared.u64 t, %1; cvt.u32.u64 %0, t; }" : "=r"(a) : "l"(p));
    return a;
}
__device__ __forceinline__ void cp_async16(uint32_t dst, const void* src) {
    asm volatile("cp.async.cg.shared.global [%0], [%1], 16;" :: "r"(dst), "l"(src) : "memory");
}
__device__ __forceinline__ void cp_async8(uint32_t dst, const void* src) {
    asm volatile("cp.async.ca.shared.global [%0], [%1], 8;" :: "r"(dst), "l"(src) : "memory");
}
#define CP_COMMIT() asm volatile("cp.async.commit_group;" ::: "memory")
#define CP_WAIT0()  asm volatile("cp.async.wait_group 0;" ::: "memory")

// m16n8k8 tf32 MMA
__device__ __forceinline__ void mma8(float* d, const uint32_t* a, uint32_t b0, uint32_t b1) {
    asm volatile("mma.sync.aligned.m16n8k8.row.col.f32.tf32.tf32.f32 "
                 "{%0,%1,%2,%3}, {%4,%5,%6,%7}, {%8,%9}, {%0,%1,%2,%3};"
                 : "+f"(d[0]), "+f"(d[1]), "+f"(d[2]), "+f"(d[3])
                 : "r"(a[0]), "r"(a[1]), "r"(a[2]), "r"(a[3]), "r"(b0), "r"(b1));
}

__device__ __forceinline__ void ffma2(ull& acc, ull a, ull b) {
    asm("fma.rn.f32x2 %0, %1, %2, %0;" : "+l"(acc) : "l"(a), "l"(b));
}
__device__ __forceinline__ ull fadd2(ull a, ull b) {
    ull d; asm("add.rn.f32x2 %0, %1, %2;" : "=l"(d) : "l"(a), "l"(b)); return d;
}
__device__ __forceinline__ void unpack2(float& lo, float& hi, ull v) {
    asm("mov.b64 {%0, %1}, %2;" : "=f"(lo), "=f"(hi) : "l"(v));
}
// fast activations via HW tanh
__device__ __forceinline__ float tanh_fast(float x) {
    float y; asm("tanh.approx.f32 %0, %1;" : "=f"(y) : "f"(x)); return y;
}
__device__ __forceinline__ float fsigmoid(float x) { return fmaf(tanh_fast(0.5f * x), 0.5f, 0.5f); }
__device__ __forceinline__ float ftanh(float x)    { return tanh_fast(x); }

// ---------------------------------------------------------------------------
// prep_b: split W_ih (+bias as K-col 182) into tf32-exact hi + f32 lo.
// Pair-interleaved k inside each k8 group.
// ---------------------------------------------------------------------------
__global__ void prep_b(const float* __restrict__ wih, const float* __restrict__ bias)
{
    int idx = blockIdx.x * 256 + threadIdx.x;      // 36864
    if (idx >= NCHUNK * G3 * KC) return;
    int c   = idx / (G3 * KC);
    int rem = idx % (G3 * KC);
    int n   = rem / KC;
    int lc  = rem % KC;
    int ks = lc >> 3, p = (lc & 7) >> 1, e = lc & 1;
    int k = c * KC + ks * 8 + p + 4 * e;
    float w = (k < IN_DIM) ? wih[n * IN_DIM + k] : ((k == IN_DIM) ? bias[n] : 0.f);
    float hi = __uint_as_float(__float_as_uint(w) & 0xFFFFE000u);
    g_bh[idx] = hi;
    g_bl[idx] = w - hi;
}

// ---------------------------------------------------------------------------
// ig_mma: R13/R7 version VERBATIM (best measured, ~490us) — single A buffer,
// occ 2. smem: A[128][40] | Bh[192][40] | Bl[192][40] = 80KB
// ---------------------------------------------------------------------------
#define A_STRIDE 40
#define SMO_A   0u
#define SMO_BH  20480u
#define SMO_BL  51200u
#define SM_TOT  81920u

__global__ __launch_bounds__(256, 2) void ig_mma(const float* __restrict__ X)
{
    extern __shared__ __align__(16) float smem[];
    float* As = smem;                        // [128][40]
    float* Bh = smem + SMO_BH / 4;           // [192][40]
    float* Bl = smem + SMO_BL / 4;
    const uint32_t sb = smem_u32(smem);

    const int tid  = threadIdx.x;
    const int wid  = tid >> 5;
    const int lane = tid & 31;
    const int mBase = blockIdx.x * M_TILE;

    const int wm = (wid & 3) * 32;
    const int wn = (wid >> 2) * 96;
    const int lr = lane >> 2;
    const int lc = lane & 3;

    float acc[2][12][4];
#pragma unroll
    for (int mf = 0; mf < 2; mf++)
#pragma unroll
        for (int nt = 0; nt < 12; nt++)
#pragma unroll
            for (int q = 0; q < 4; q++) acc[mf][nt][q] = 0.f;

    const int row  = tid >> 1;
    const int half = tid & 1;
    const float* xrow = X + (size_t)(mBase + row) * IN_DIM;

    for (int c = 0; c < NCHUNK; c++) {
        const float* srcH = g_bh + (size_t)c * G3 * KC;
        const float* srcL = g_bl + (size_t)c * G3 * KC;
#pragma unroll
        for (int j = 0; j < 6; j++) {
            int id = tid + j * 256;
            int n  = id >> 3;
            int q4 = (id & 7) * 4;
            uint32_t doff = (uint32_t)(n * A_STRIDE + q4) * 4u;
            cp_async16(sb + SMO_BH + doff, srcH + n * KC + q4);
            cp_async16(sb + SMO_BL + doff, srcL + n * KC + q4);
        }
        const int kb = c * KC + half * 16;
        const uint32_t aBase = sb + SMO_A + (uint32_t)(row * A_STRIDE + half * 16) * 4u;
#pragma unroll
        for (int i = 0; i < 8; i++) {
            int kk = kb + 2 * i;
            if (kk + 1 < IN_DIM)
                cp_async8(aBase + (uint32_t)(8 * i), xrow + kk);
        }
        if (c == NCHUNK - 1 && half == 1) {
            float* ar = As + row * A_STRIDE;
            ar[22] = 1.0f;
#pragma unroll
            for (int i = 23; i < 32; i++) ar[i] = 0.f;
        }
        CP_COMMIT();
        CP_WAIT0();
        __syncthreads();

#pragma unroll
        for (int ks = 0; ks < 4; ks++) {
            uint32_t a[2][4];
#pragma unroll
            for (int mf = 0; mf < 2; mf++) {
                const float* ar  = As + (wm + mf * 16 + lr) * A_STRIDE + ks * 8 + lc;
                const float* ar8 = ar + 8 * A_STRIDE;
                a[mf][0] = __float_as_uint(ar[0]);
                a[mf][1] = __float_as_uint(ar8[0]);
                a[mf][2] = __float_as_uint(ar[4]);
                a[mf][3] = __float_as_uint(ar8[4]);
            }
#pragma unroll
            for (int nt = 0; nt < 12; nt++) {
                int boff = (wn + nt * 8 + lr) * A_STRIDE + ks * 8 + 2 * lc;
                uint2 bh = *(const uint2*)(Bh + boff);
                uint2 bl = *(const uint2*)(Bl + boff);
                mma8(acc[0][nt], a[0], bh.x, bh.y);
                mma8(acc[1][nt], a[1], bh.x, bh.y);
                mma8(acc[0][nt], a[0], bl.x, bl.y);
                mma8(acc[1][nt], a[1], bl.x, bl.y);
            }
        }
        __syncthreads();
    }

#pragma unroll
    for (int mf = 0; mf < 2; mf++) {
        const int r0 = mBase + wm + mf * 16 + lr;
#pragma unroll
        for (int nt = 0; nt < 12; nt++) {
            const int col = wn + nt * 8 + 2 * lc;
            *(float2*)&g_ig[(size_t)r0 * G3 + col] =
                make_float2(acc[mf][nt][0], acc[mf][nt][1]);
            *(float2*)&g_ig[(size_t)(r0 + 8) * G3 + col] =
                make_float2(acc[mf][nt][2], acc[mf][nt][3]);
        }
    }
}

// ---------------------------------------------------------------------------
// GRU scan: 192 threads (6 warps -> covers all 4 SMSPs), one gate-row per
// thread (32 ffma2). Warp-uniform gate roles: warps 0-1 = r, 2-3 = z,
// 4-5 = n. tanh.approx activations, uniform 4-deep ig prefetch, fadd2
// reduction, r/z cross to n-threads via smem (2 barriers/step).
// ---------------------------------------------------------------------------
__global__ __launch_bounds__(192) void gru_scan(const float* __restrict__ whh,
                                                const float* __restrict__ bias_n,
                                                const float* __restrict__ wout,
                                                const float* __restrict__ out_bias,
                                                float* __restrict__ out)
{
    const int b = blockIdx.x;
    const int j = threadIdx.x;                 // 0..191
    const int wg = j >> 6;                     // 0=r, 1=z, 2=n
    const int u  = j & 63;                     // hidden unit

    __shared__ float sh_h[2][64];
    __shared__ float sh_r[64];
    __shared__ float sh_z[64];

    ull wp[32];
#pragma unroll
    for (int q = 0; q < 32; q++) wp[q] = *(const ull*)&whh[j * 64 + 2 * q];
    const float bn = (wg == 2) ? bias_n[u] : 0.f;

    if (j < 64) sh_h[0][j] = 0.f;

    const float* igp = g_ig + (size_t)b * T_LEN * G3 + j;
    float pig[4];
#pragma unroll
    for (int v = 0; v < 4; v++) pig[v] = igp[(size_t)v * G3];
    __syncthreads();

    int p = 0;
    for (int t = 0; t < T_LEN; t += 4) {
#pragma unroll
        for (int v = 0; v < 4; v++) {
            const float igc = pig[v];
            const int tn = t + 4 + v;
            if (tn < T_LEN) pig[v] = igp[(size_t)tn * G3];

            // 64-dot against shared h: 32 ffma2, 4 chains
            ull a0 = 0, a1 = 0, a2 = 0, a3 = 0;
            const float* hb = sh_h[p];
#pragma unroll
            for (int q = 0; q < 32; q += 4) {
                ulonglong2 h01 = *(const ulonglong2*)&hb[2 * q];
                ulonglong2 h23 = *(const ulonglong2*)&hb[2 * q + 4];
                ffma2(a0, wp[q],     h01.x);
                ffma2(a1, wp[q + 1], h01.y);
                ffma2(a2, wp[q + 2], h23.x);
                ffma2(a3, wp[q + 3], h23.y);
            }
            ull s = fadd2(fadd2(a0, a1), fadd2(a2, a3));
            float x0, x1; unpack2(x0, x1, s);
            const float hg = x0 + x1;

            if (wg == 0)      sh_r[u] = fsigmoid(igc + hg);
            else if (wg == 1) sh_z[u] = fsigmoid(igc + hg);
            __syncthreads();

            if (wg == 2) {
                const float r = sh_r[u];
                const float n = ftanh(igc + r * (hg + bn));
                const float z = sh_z[u];
                const float h = sh_h[p][u];
                sh_h[1 - p][u] = n + z * (h - n);
            }
            __syncthreads();
            p ^= 1;
        }
    }

    // readout (T_LEN even -> final h in sh_h[0])
    if (j < 2) {
        float acc = 0.f;
        const float* hf = sh_h[0];
#pragma unroll 8
        for (int k = 0; k < 64; k++) acc += wout[j * 64 + k] * hf[k];
        out[b * 2 + j] = fsigmoid(acc + out_bias[j]);
    }
}

// ---------------------------------------------------------------------------
extern "C" void kernel_launch(void* const* d_in, const int* in_sizes, int n_in,
                              void* d_out, int out_size)
{
    const float* x        = (const float*)d_in[0];
    const float* wih      = (const float*)d_in[1];
    const float* whh      = (const float*)d_in[2];
    const float* bias     = (const float*)d_in[3];
    const float* bias_n   = (const float*)d_in[4];
    const float* wout     = (const float*)d_in[5];
    const float* out_bias = (const float*)d_in[6];
    float* out = (float*)d_out;

    cudaFuncSetAttribute(ig_mma, cudaFuncAttributeMaxDynamicSharedMemorySize, SM_TOT);

    prep_b<<<(NCHUNK * G3 * KC + 255) / 256, 256>>>(wih, bias);
    ig_mma<<<(B_SZ * T_LEN) / M_TILE, 256, SM_TOT>>>(x);
    gru_scan<<<B_SZ, 192>>>(whh, bias_n, wout, out_bias, out);
}

// round 16
// speedup vs baseline: 1.2538x; 1.2538x over previous
#include <cuda_runtime.h>
#include <cstdint>

#define T_LEN 2048
#define B_SZ  256
#define IN_DIM 182
#define G3     192
#define KC     32
#define NCHUNK 6
#define M_TILE 128

typedef unsigned long long ull;

// scratch: IG[B*T,192] (~403MB) + pair-interleaved split-B images [chunk][192][32]
__device__ float g_ig[(size_t)B_SZ * T_LEN * G3];
__device__ __align__(16) float g_bh[NCHUNK * G3 * KC];
__device__ __align__(16) float g_bl[NCHUNK * G3 * KC];

// ---------------- helpers ----------------
__device__ __forceinline__ uint32_t smem_u32(const void* p) {
    uint32_t a;
    asm("{ .reg .u64 t; cvta.to.shared.u64 t, %1; cvt.u32.u64 %0, t; }" : "=r"(a) : "l"(p));
    return a;
}
__device__ __forceinline__ void cp_async16(uint32_t dst, const void* src) {
    asm volatile("cp.async.cg.shared.global [%0], [%1], 16;" :: "r"(dst), "l"(src) : "memory");
}
__device__ __forceinline__ void cp_async8(uint32_t dst, const void* src) {
    asm volatile("cp.async.ca.shared.global [%0], [%1], 8;" :: "r"(dst), "l"(src) : "memory");
}
#define CP_COMMIT() asm volatile("cp.async.commit_group;" ::: "memory")
#define CP_WAIT0()  asm volatile("cp.async.wait_group 0;" ::: "memory")

// m16n8k8 tf32 MMA
__device__ __forceinline__ void mma8(float* d, const uint32_t* a, uint32_t b0, uint32_t b1) {
    asm volatile("mma.sync.aligned.m16n8k8.row.col.f32.tf32.tf32.f32 "
                 "{%0,%1,%2,%3}, {%4,%5,%6,%7}, {%8,%9}, {%0,%1,%2,%3};"
                 : "+f"(d[0]), "+f"(d[1]), "+f"(d[2]), "+f"(d[3])
                 : "r"(a[0]), "r"(a[1]), "r"(a[2]), "r"(a[3]), "r"(b0), "r"(b1));
}

__device__ __forceinline__ void ffma2(ull& acc, ull a, ull b) {
    asm("fma.rn.f32x2 %0, %1, %2, %0;" : "+l"(acc) : "l"(a), "l"(b));
}
__device__ __forceinline__ void unpack2(float& lo, float& hi, ull v) {
    asm("mov.b64 {%0, %1}, %2;" : "=f"(lo), "=f"(hi) : "l"(v));
}
// fast activations via HW tanh
__device__ __forceinline__ float tanh_fast(float x) {
    float y; asm("tanh.approx.f32 %0, %1;" : "=f"(y) : "f"(x)); return y;
}
__device__ __forceinline__ float fsigmoid(float x) { return fmaf(tanh_fast(0.5f * x), 0.5f, 0.5f); }
__device__ __forceinline__ float ftanh(float x)    { return tanh_fast(x); }

// ---------------------------------------------------------------------------
// prep_b: split W_ih (+bias as K-col 182) into tf32-exact hi + f32 lo.
// ---------------------------------------------------------------------------
__global__ void prep_b(const float* __restrict__ wih, const float* __restrict__ bias)
{
    int idx = blockIdx.x * 256 + threadIdx.x;      // 36864
    if (idx >= NCHUNK * G3 * KC) return;
    int c   = idx / (G3 * KC);
    int rem = idx % (G3 * KC);
    int n   = rem / KC;
    int lc  = rem % KC;
    int ks = lc >> 3, p = (lc & 7) >> 1, e = lc & 1;
    int k = c * KC + ks * 8 + p + 4 * e;
    float w = (k < IN_DIM) ? wih[n * IN_DIM + k] : ((k == IN_DIM) ? bias[n] : 0.f);
    float hi = __uint_as_float(__float_as_uint(w) & 0xFFFFE000u);
    g_bh[idx] = hi;
    g_bl[idx] = w - hi;
}

// ---------------------------------------------------------------------------
// ig_mma: R13/R7 version VERBATIM (best measured, ~490us) — single A buffer,
// occ 2. smem: A[128][40] | Bh[192][40] | Bl[192][40] = 80KB
// ---------------------------------------------------------------------------
#define A_STRIDE 40
#define SMO_A   0u
#define SMO_BH  20480u
#define SMO_BL  51200u
#define SM_TOT  81920u

__global__ __launch_bounds__(256, 2) void ig_mma(const float* __restrict__ X)
{
    extern __shared__ __align__(16) float smem[];
    float* As = smem;                        // [128][40]
    float* Bh = smem + SMO_BH / 4;           // [192][40]
    float* Bl = smem + SMO_BL / 4;
    const uint32_t sb = smem_u32(smem);

    const int tid  = threadIdx.x;
    const int wid  = tid >> 5;
    const int lane = tid & 31;
    const int mBase = blockIdx.x * M_TILE;

    const int wm = (wid & 3) * 32;
    const int wn = (wid >> 2) * 96;
    const int lr = lane >> 2;
    const int lc = lane & 3;

    float acc[2][12][4];
#pragma unroll
    for (int mf = 0; mf < 2; mf++)
#pragma unroll
        for (int nt = 0; nt < 12; nt++)
#pragma unroll
            for (int q = 0; q < 4; q++) acc[mf][nt][q] = 0.f;

    const int row  = tid >> 1;
    const int half = tid & 1;
    const float* xrow = X + (size_t)(mBase + row) * IN_DIM;

    for (int c = 0; c < NCHUNK; c++) {
        const float* srcH = g_bh + (size_t)c * G3 * KC;
        const float* srcL = g_bl + (size_t)c * G3 * KC;
#pragma unroll
        for (int j = 0; j < 6; j++) {
            int id = tid + j * 256;
            int n  = id >> 3;
            int q4 = (id & 7) * 4;
            uint32_t doff = (uint32_t)(n * A_STRIDE + q4) * 4u;
            cp_async16(sb + SMO_BH + doff, srcH + n * KC + q4);
            cp_async16(sb + SMO_BL + doff, srcL + n * KC + q4);
        }
        const int kb = c * KC + half * 16;
        const uint32_t aBase = sb + SMO_A + (uint32_t)(row * A_STRIDE + half * 16) * 4u;
#pragma unroll
        for (int i = 0; i < 8; i++) {
            int kk = kb + 2 * i;
            if (kk + 1 < IN_DIM)
                cp_async8(aBase + (uint32_t)(8 * i), xrow + kk);
        }
        if (c == NCHUNK - 1 && half == 1) {
            float* ar = As + row * A_STRIDE;
            ar[22] = 1.0f;
#pragma unroll
            for (int i = 23; i < 32; i++) ar[i] = 0.f;
        }
        CP_COMMIT();
        CP_WAIT0();
        __syncthreads();

#pragma unroll
        for (int ks = 0; ks < 4; ks++) {
            uint32_t a[2][4];
#pragma unroll
            for (int mf = 0; mf < 2; mf++) {
                const float* ar  = As + (wm + mf * 16 + lr) * A_STRIDE + ks * 8 + lc;
                const float* ar8 = ar + 8 * A_STRIDE;
                a[mf][0] = __float_as_uint(ar[0]);
                a[mf][1] = __float_as_uint(ar8[0]);
                a[mf][2] = __float_as_uint(ar[4]);
                a[mf][3] = __float_as_uint(ar8[4]);
            }
#pragma unroll
            for (int nt = 0; nt < 12; nt++) {
                int boff = (wn + nt * 8 + lr) * A_STRIDE + ks * 8 + 2 * lc;
                uint2 bh = *(const uint2*)(Bh + boff);
                uint2 bl = *(const uint2*)(Bl + boff);
                mma8(acc[0][nt], a[0], bh.x, bh.y);
                mma8(acc[1][nt], a[1], bh.x, bh.y);
                mma8(acc[0][nt], a[0], bl.x, bl.y);
                mma8(acc[1][nt], a[1], bl.x, bl.y);
            }
        }
        __syncthreads();
    }

#pragma unroll
    for (int mf = 0; mf < 2; mf++) {
        const int r0 = mBase + wm + mf * 16 + lr;
#pragma unroll
        for (int nt = 0; nt < 12; nt++) {
            const int col = wn + nt * 8 + 2 * lc;
            *(float2*)&g_ig[(size_t)r0 * G3 + col] =
                make_float2(acc[mf][nt][0], acc[mf][nt][1]);
            *(float2*)&g_ig[(size_t)(r0 + 8) * G3 + col] =
                make_float2(acc[mf][nt][2], acc[mf][nt][3]);
        }
    }
}

// ---------------------------------------------------------------------------
// GRU scan: 2 batches per CTA, 128 threads, grid=128 (<=148 SMs -> 1 CTA/SM,
// 1 warp/SMSP). Warps 0-1 = batch 2b (R12 body verbatim), warps 2-3 = batch
// 2b+1. Shared __syncthreads is lock-step across both sub-batches.
// ---------------------------------------------------------------------------
__global__ __launch_bounds__(128) void gru_scan(const float* __restrict__ whh,
                                                const float* __restrict__ bias_n,
                                                const float* __restrict__ wout,
                                                const float* __restrict__ out_bias,
                                                float* __restrict__ out)
{
    const int tid = threadIdx.x;
    const int sub = tid >> 6;                  // 0 or 1: sub-batch
    const int j   = tid & 63;                  // hidden unit
    const int b   = blockIdx.x * 2 + sub;

    __shared__ float sh_h[2][2][64];           // [sub][phase][unit]

    ull wr[32], wz[32], wn[32];
#pragma unroll
    for (int q = 0; q < 32; q++) {
        wr[q] = *(const ull*)&whh[(j)        * 64 + 2 * q];
        wz[q] = *(const ull*)&whh[(64 + j)   * 64 + 2 * q];
        wn[q] = *(const ull*)&whh[(128 + j)  * 64 + 2 * q];
    }
    const float bn = bias_n[j];

    float hreg = 0.f;
    sh_h[sub][0][j] = 0.f;

    const float* igp = g_ig + (size_t)b * T_LEN * G3;
    float pr[4], pz[4], pn[4];
#pragma unroll
    for (int u = 0; u < 4; u++) {
        const float* g = igp + (size_t)u * G3;
        pr[u] = g[j]; pz[u] = g[64 + j]; pn[u] = g[128 + j];
    }
    __syncthreads();

    int p = 0;
    for (int t = 0; t < T_LEN; t += 4) {
#pragma unroll
        for (int u = 0; u < 4; u++) {
            const float igr = pr[u], igz = pz[u], ign = pn[u];
            const int tn = t + 4 + u;
            if (tn < T_LEN) {
                const float* g = igp + (size_t)tn * G3;
                pr[u] = g[j]; pz[u] = g[64 + j]; pn[u] = g[128 + j];
            }

            ull ar0 = 0, ar1 = 0, az0 = 0, az1 = 0, an0 = 0, an1 = 0;
            const float* hb = sh_h[sub][p];
#pragma unroll
            for (int q = 0; q < 32; q += 2) {
                ulonglong2 h2 = *(const ulonglong2*)&hb[2 * q];
                ffma2(ar0, wr[q], h2.x); ffma2(ar1, wr[q + 1], h2.y);
                ffma2(az0, wz[q], h2.x); ffma2(az1, wz[q + 1], h2.y);
                ffma2(an0, wn[q], h2.x); ffma2(an1, wn[q + 1], h2.y);
            }
            float x0, x1, y0, y1;
            unpack2(x0, x1, ar0); unpack2(y0, y1, ar1);
            const float hgr = (x0 + x1) + (y0 + y1);
            unpack2(x0, x1, az0); unpack2(y0, y1, az1);
            const float hgz = (x0 + x1) + (y0 + y1);
            unpack2(x0, x1, an0); unpack2(y0, y1, an1);
            const float hgn = (x0 + x1) + (y0 + y1);

            const float r = fsigmoid(igr + hgr);
            const float z = fsigmoid(igz + hgz);
            const float n = ftanh(ign + r * (hgn + bn));
            hreg = n + z * (hreg - n);

            sh_h[sub][1 - p][j] = hreg;
            __syncthreads();
            p ^= 1;
        }
    }

    // readout
    sh_h[sub][0][j] = hreg;
    __syncthreads();
    if (j < 2) {
        float acc = 0.f;
        const float* hf = sh_h[sub][0];
#pragma unroll 8
        for (int k = 0; k < 64; k++) acc += wout[j * 64 + k] * hf[k];
        out[b * 2 + j] = fsigmoid(acc + out_bias[j]);
    }
}

// ---------------------------------------------------------------------------
extern "C" void kernel_launch(void* const* d_in, const int* in_sizes, int n_in,
                              void* d_out, int out_size)
{
    const float* x        = (const float*)d_in[0];
    const float* wih      = (const float*)d_in[1];
    const float* whh      = (const float*)d_in[2];
    const float* bias     = (const float*)d_in[3];
    const float* bias_n   = (const float*)d_in[4];
    const float* wout     = (const float*)d_in[5];
    const float* out_bias = (const float*)d_in[6];
    float* out = (float*)d_out;

    cudaFuncSetAttribute(ig_mma, cudaFuncAttributeMaxDynamicSharedMemorySize, SM_TOT);

    prep_b<<<(NCHUNK * G3 * KC + 255) / 256, 256>>>(wih, bias);
    ig_mma<<<(B_SZ * T_LEN) / M_TILE, 256, SM_TOT>>>(x);
    gru_scan<<<B_SZ / 2, 128>>>(whh, bias_n, wout, out_bias, out);
}

// round 17
// speedup vs baseline: 1.4316x; 1.1418x over previous
#include <cuda_runtime.h>
#include <cstdint>

#define T_LEN 2048
#define B_SZ  256
#define IN_DIM 182
#define G3     192
#define KC     32
#define NCHUNK 6
#define M_TILE 128

typedef unsigned long long ull;

// scratch: IG[B*T,192] (~403MB) + pair-interleaved tf32 B image [chunk][192][32]
__device__ float g_ig[(size_t)B_SZ * T_LEN * G3];
__device__ __align__(16) float g_bh[NCHUNK * G3 * KC];

// ---------------- helpers ----------------
__device__ __forceinline__ uint32_t smem_u32(const void* p) {
    uint32_t a;
    asm("{ .reg .u64 t; cvta.to.shared.u64 t, %1; cvt.u32.u64 %0, t; }" : "=r"(a) : "l"(p));
    return a;
}
__device__ __forceinline__ void cp_async16(uint32_t dst, const void* src) {
    asm volatile("cp.async.cg.shared.global [%0], [%1], 16;" :: "r"(dst), "l"(src) : "memory");
}
__device__ __forceinline__ void cp_async8(uint32_t dst, const void* src) {
    asm volatile("cp.async.ca.shared.global [%0], [%1], 8;" :: "r"(dst), "l"(src) : "memory");
}
#define CP_COMMIT() asm volatile("cp.async.commit_group;" ::: "memory")
#define CP_WAIT0()  asm volatile("cp.async.wait_group 0;" ::: "memory")

// m16n8k8 tf32 MMA
__device__ __forceinline__ void mma8(float* d, const uint32_t* a, uint32_t b0, uint32_t b1) {
    asm volatile("mma.sync.aligned.m16n8k8.row.col.f32.tf32.tf32.f32 "
                 "{%0,%1,%2,%3}, {%4,%5,%6,%7}, {%8,%9}, {%0,%1,%2,%3};"
                 : "+f"(d[0]), "+f"(d[1]), "+f"(d[2]), "+f"(d[3])
                 : "r"(a[0]), "r"(a[1]), "r"(a[2]), "r"(a[3]), "r"(b0), "r"(b1));
}

__device__ __forceinline__ void ffma2(ull& acc, ull a, ull b) {
    asm("fma.rn.f32x2 %0, %1, %2, %0;" : "+l"(acc) : "l"(a), "l"(b));
}
__device__ __forceinline__ void unpack2(float& lo, float& hi, ull v) {
    asm("mov.b64 {%0, %1}, %2;" : "=f"(lo), "=f"(hi) : "l"(v));
}
// fast activations via HW tanh
__device__ __forceinline__ float tanh_fast(float x) {
    float y; asm("tanh.approx.f32 %0, %1;" : "=f"(y) : "f"(x)); return y;
}
__device__ __forceinline__ float fsigmoid(float x) { return fmaf(tanh_fast(0.5f * x), 0.5f, 0.5f); }
__device__ __forceinline__ float ftanh(float x)    { return tanh_fast(x); }

// ---------------------------------------------------------------------------
// prep_b: round W_ih (+bias as K-col 182) to tf32 image, pair-interleaved k.
// (Single-term: B truncation error is ~A's, adds in quadrature — measured
//  A-only gives 3.2e-5 final, so expect ~5e-5-1e-4.)
// ---------------------------------------------------------------------------
__global__ void prep_b(const float* __restrict__ wih, const float* __restrict__ bias)
{
    int idx = blockIdx.x * 256 + threadIdx.x;      // 36864
    if (idx >= NCHUNK * G3 * KC) return;
    int c   = idx / (G3 * KC);
    int rem = idx % (G3 * KC);
    int n   = rem / KC;
    int lc  = rem % KC;
    int ks = lc >> 3, p = (lc & 7) >> 1, e = lc & 1;
    int k = c * KC + ks * 8 + p + 4 * e;
    float w = (k < IN_DIM) ? wih[n * IN_DIM + k] : ((k == IN_DIM) ? bias[n] : 0.f);
    g_bh[idx] = w;   // raw f32; HW truncates to tf32 inside the MMA
}

// ---------------------------------------------------------------------------
// ig_mma: single-term tf32 GEMM (half the MMAs of the 2-term version).
// smem: A[128][40]=20KB | Bh[192][40]=30KB -> 50KB, occ 2.
// ---------------------------------------------------------------------------
#define A_STRIDE 40
#define SMO_A   0u
#define SMO_BH  20480u
#define SM_TOT  51200u

__global__ __launch_bounds__(256, 2) void ig_mma(const float* __restrict__ X)
{
    extern __shared__ __align__(16) float smem[];
    float* As = smem;                        // [128][40]
    float* Bh = smem + SMO_BH / 4;           // [192][40]
    const uint32_t sb = smem_u32(smem);

    const int tid  = threadIdx.x;
    const int wid  = tid >> 5;
    const int lane = tid & 31;
    const int mBase = blockIdx.x * M_TILE;

    const int wm = (wid & 3) * 32;
    const int wn = (wid >> 2) * 96;
    const int lr = lane >> 2;
    const int lc = lane & 3;

    float acc[2][12][4];
#pragma unroll
    for (int mf = 0; mf < 2; mf++)
#pragma unroll
        for (int nt = 0; nt < 12; nt++)
#pragma unroll
            for (int q = 0; q < 4; q++) acc[mf][nt][q] = 0.f;

    const int row  = tid >> 1;
    const int half = tid & 1;
    const float* xrow = X + (size_t)(mBase + row) * IN_DIM;

    for (int c = 0; c < NCHUNK; c++) {
        // ---- stage B: 6 x 16B per thread ----
        const float* srcH = g_bh + (size_t)c * G3 * KC;
#pragma unroll
        for (int j = 0; j < 6; j++) {
            int id = tid + j * 256;
            int n  = id >> 3;
            int q4 = (id & 7) * 4;
            uint32_t doff = (uint32_t)(n * A_STRIDE + q4) * 4u;
            cp_async16(sb + SMO_BH + doff, srcH + n * KC + q4);
        }
        // ---- stage A: 8 x 8B per thread (X rows are 8B-aligned) ----
        const int kb = c * KC + half * 16;
        const uint32_t aBase = sb + SMO_A + (uint32_t)(row * A_STRIDE + half * 16) * 4u;
#pragma unroll
        for (int i = 0; i < 8; i++) {
            int kk = kb + 2 * i;
            if (kk + 1 < IN_DIM)
                cp_async8(aBase + (uint32_t)(8 * i), xrow + kk);
        }
        if (c == NCHUNK - 1 && half == 1) {
            float* ar = As + row * A_STRIDE;
            ar[22] = 1.0f;
#pragma unroll
            for (int i = 23; i < 32; i++) ar[i] = 0.f;
        }
        CP_COMMIT();
        CP_WAIT0();
        __syncthreads();

        // ---- compute: 4 k8-steps, single term ----
#pragma unroll
        for (int ks = 0; ks < 4; ks++) {
            uint32_t a[2][4];
#pragma unroll
            for (int mf = 0; mf < 2; mf++) {
                const float* ar  = As + (wm + mf * 16 + lr) * A_STRIDE + ks * 8 + lc;
                const float* ar8 = ar + 8 * A_STRIDE;
                a[mf][0] = __float_as_uint(ar[0]);
                a[mf][1] = __float_as_uint(ar8[0]);
                a[mf][2] = __float_as_uint(ar[4]);
                a[mf][3] = __float_as_uint(ar8[4]);
            }
#pragma unroll
            for (int nt = 0; nt < 12; nt++) {
                int boff = (wn + nt * 8 + lr) * A_STRIDE + ks * 8 + 2 * lc;
                uint2 bh = *(const uint2*)(Bh + boff);
                mma8(acc[0][nt], a[0], bh.x, bh.y);
                mma8(acc[1][nt], a[1], bh.x, bh.y);
            }
        }
        __syncthreads();
    }

    // ---- epilogue ----
#pragma unroll
    for (int mf = 0; mf < 2; mf++) {
        const int r0 = mBase + wm + mf * 16 + lr;
#pragma unroll
        for (int nt = 0; nt < 12; nt++) {
            const int col = wn + nt * 8 + 2 * lc;
            *(float2*)&g_ig[(size_t)r0 * G3 + col] =
                make_float2(acc[mf][nt][0], acc[mf][nt][1]);
            *(float2*)&g_ig[(size_t)(r0 + 8) * G3 + col] =
                make_float2(acc[mf][nt][2], acc[mf][nt][3]);
        }
    }
}

// ---------------------------------------------------------------------------
// GRU scan: R12 version VERBATIM (best measured, 580us) — 64 threads,
// weights in registers, tanh.approx, 1 barrier/step, 4-deep ig prefetch.
// ---------------------------------------------------------------------------
__global__ __launch_bounds__(64) void gru_scan(const float* __restrict__ whh,
                                               const float* __restrict__ bias_n,
                                               const float* __restrict__ wout,
                                               const float* __restrict__ out_bias,
                                               float* __restrict__ out)
{
    const int b = blockIdx.x;
    const int j = threadIdx.x;                 // 0..63

    __shared__ float sh_h[2][64];

    ull wr[32], wz[32], wn[32];
#pragma unroll
    for (int q = 0; q < 32; q++) {
        wr[q] = *(const ull*)&whh[(j)        * 64 + 2 * q];
        wz[q] = *(const ull*)&whh[(64 + j)   * 64 + 2 * q];
        wn[q] = *(const ull*)&whh[(128 + j)  * 64 + 2 * q];
    }
    const float bn = bias_n[j];

    float hreg = 0.f;
    sh_h[0][j] = 0.f;

    const float* igp = g_ig + (size_t)b * T_LEN * G3;
    float pr[4], pz[4], pn[4];
#pragma unroll
    for (int u = 0; u < 4; u++) {
        const float* g = igp + (size_t)u * G3;
        pr[u] = g[j]; pz[u] = g[64 + j]; pn[u] = g[128 + j];
    }
    __syncthreads();

    int p = 0;
    for (int t = 0; t < T_LEN; t += 4) {
#pragma unroll
        for (int u = 0; u < 4; u++) {
            const float igr = pr[u], igz = pz[u], ign = pn[u];
            const int tn = t + 4 + u;
            if (tn < T_LEN) {
                const float* g = igp + (size_t)tn * G3;
                pr[u] = g[j]; pz[u] = g[64 + j]; pn[u] = g[128 + j];
            }

            ull ar0 = 0, ar1 = 0, az0 = 0, az1 = 0, an0 = 0, an1 = 0;
            const float* hb = sh_h[p];
#pragma unroll
            for (int q = 0; q < 32; q += 2) {
                ulonglong2 h2 = *(const ulonglong2*)&hb[2 * q];
                ffma2(ar0, wr[q], h2.x); ffma2(ar1, wr[q + 1], h2.y);
                ffma2(az0, wz[q], h2.x); ffma2(az1, wz[q + 1], h2.y);
                ffma2(an0, wn[q], h2.x); ffma2(an1, wn[q + 1], h2.y);
            }
            float x0, x1, y0, y1;
            unpack2(x0, x1, ar0); unpack2(y0, y1, ar1);
            const float hgr = (x0 + x1) + (y0 + y1);
            unpack2(x0, x1, az0); unpack2(y0, y1, az1);
            const float hgz = (x0 + x1) + (y0 + y1);
            unpack2(x0, x1, an0); unpack2(y0, y1, an1);
            const float hgn = (x0 + x1) + (y0 + y1);

            const float r = fsigmoid(igr + hgr);
            const float z = fsigmoid(igz + hgz);
            const float n = ftanh(ign + r * (hgn + bn));
            hreg = n + z * (hreg - n);

            sh_h[1 - p][j] = hreg;
            __syncthreads();
            p ^= 1;
        }
    }

    sh_h[0][j] = hreg;
    __syncthreads();
    if (j < 2) {
        float acc = 0.f;
#pragma unroll 8
        for (int k = 0; k < 64; k++) acc += wout[j * 64 + k] * sh_h[0][k];
        out[b * 2 + j] = fsigmoid(acc + out_bias[j]);
    }
}

// ---------------------------------------------------------------------------
extern "C" void kernel_launch(void* const* d_in, const int* in_sizes, int n_in,
                              void* d_out, int out_size)
{
    const float* x        = (const float*)d_in[0];
    const float* wih      = (const float*)d_in[1];
    const float* whh      = (const float*)d_in[2];
    const float* bias     = (const float*)d_in[3];
    const float* bias_n   = (const float*)d_in[4];
    const float* wout     = (const float*)d_in[5];
    const float* out_bias = (const float*)d_in[6];
    float* out = (float*)d_out;

    cudaFuncSetAttribute(ig_mma, cudaFuncAttributeMaxDynamicSharedMemorySize, SM_TOT);

    prep_b<<<(NCHUNK * G3 * KC + 255) / 256, 256>>>(wih, bias);
    ig_mma<<<(B_SZ * T_LEN) / M_TILE, 256, SM_TOT>>>(x);
    gru_scan<<<B_SZ, 64>>>(whh, bias_n, wout, out_bias, out);
}